// round 1
// baseline (speedup 1.0000x reference)
#include <cuda_runtime.h>
#include <math.h>

// ---------------- scratch (allocation-free: __device__ globals) ----------------
#define MAXBUF (64*32*32*32)          // 2,097,152 floats
__device__ float g_wh  [64*32*8];     // reordered weights [ci][tap][co]
__device__ float g_wc0 [64*64*8];
__device__ float g_wr0 [64*64*27];
__device__ float g_wr1 [64*64*27];
__device__ float g_wc1 [64*64*27];
__device__ float g_wout[32*64*27];
__device__ float g_y [MAXBUF];
__device__ float g_t [MAXBUF];
__device__ float g_cA[MAXBUF];
__device__ float g_cB[64*16*16*16];

#define TX 8
#define TY 8
#define TZ 4
#define NT 256

enum { M_PLAIN = 0, M_RELU = 1, M_ADD = 2, M_HALF = 3 };

// reorder weights (O,I,taps) -> (I,taps,O) so compute can use float4 broadcast loads
__global__ void reorderw(const float* __restrict__ w, float* __restrict__ wT,
                         int cout, int cin, int taps) {
    int i = blockIdx.x * 256 + threadIdx.x;
    int n = cout * cin * taps;
    if (i >= n) return;
    int co = i / (cin * taps);
    int r  = i % (cin * taps);
    int ci = r / taps;
    int t  = r % taps;
    wT[((size_t)ci * taps + t) * cout + co] = w[i];
}

// ---------------- k3 s1 SAME conv ----------------
template<int COUT, int MODE>
__launch_bounds__(NT)
__global__ void conv3k(const float* __restrict__ in, const float* __restrict__ wT,
                       float* __restrict__ out, int d, int cin) {
    __shared__ float tile[TZ + 2][TY + 2][TX + 2];
    __shared__ __align__(16) float ws[27 * COUT];
    const int tx = threadIdx.x, ty = threadIdx.y, tz = threadIdx.z;
    const int tid = (tz * TY + ty) * TX + tx;
    const int x0 = blockIdx.x * TX, y0 = blockIdx.y * TY, z0 = blockIdx.z * TZ;
    const int d2 = d * d, d3 = d2 * d;

    float acc[COUT];
#pragma unroll
    for (int c = 0; c < COUT; ++c) acc[c] = 0.f;

    for (int ci = 0; ci < cin; ++ci) {
        __syncthreads();
        const float* inc = in + (size_t)ci * d3;
        for (int i = tid; i < (TZ + 2) * (TY + 2) * (TX + 2); i += NT) {
            int lx = i % (TX + 2);
            int r  = i / (TX + 2);
            int ly = r % (TY + 2);
            int lz = r / (TY + 2);
            int gx = x0 + lx - 1, gy = y0 + ly - 1, gz = z0 + lz - 1;
            float v = 0.f;
            if ((unsigned)gx < (unsigned)d && (unsigned)gy < (unsigned)d &&
                (unsigned)gz < (unsigned)d)
                v = inc[(size_t)gz * d2 + gy * d + gx];
            tile[lz][ly][lx] = v;
        }
        const float* wc = wT + (size_t)ci * 27 * COUT;
        for (int i = tid; i < 27 * COUT; i += NT) ws[i] = wc[i];
        __syncthreads();

#pragma unroll 1
        for (int dz = 0; dz < 3; ++dz) {
#pragma unroll
            for (int dy = 0; dy < 3; ++dy) {
#pragma unroll
                for (int dx = 0; dx < 3; ++dx) {
                    float v = tile[tz + dz][ty + dy][tx + dx];
                    const float4* wp =
                        (const float4*)(ws + ((dz * 3 + dy) * 3 + dx) * COUT);
#pragma unroll
                    for (int c4 = 0; c4 < COUT / 4; ++c4) {
                        float4 w4 = wp[c4];
                        acc[c4 * 4 + 0] = fmaf(v, w4.x, acc[c4 * 4 + 0]);
                        acc[c4 * 4 + 1] = fmaf(v, w4.y, acc[c4 * 4 + 1]);
                        acc[c4 * 4 + 2] = fmaf(v, w4.z, acc[c4 * 4 + 2]);
                        acc[c4 * 4 + 3] = fmaf(v, w4.w, acc[c4 * 4 + 3]);
                    }
                }
            }
        }
    }

    const int gx = x0 + tx, gy = y0 + ty, gz = z0 + tz;
    const size_t idx = (size_t)gz * d2 + gy * d + gx;
#pragma unroll
    for (int c = 0; c < COUT; ++c) {
        float v = acc[c];
        if (MODE == M_RELU) v = fmaxf(v, 0.f);
        if (MODE == M_HALF) v *= 0.5f;
        float* o = out + (size_t)c * d3 + idx;
        if (MODE == M_ADD) *o += v; else *o = v;
    }
}

// ---------------- k2 s2 VALID conv ----------------
template<int COUT, int MODE>
__launch_bounds__(NT)
__global__ void conv2k(const float* __restrict__ in, const float* __restrict__ wT,
                       float* __restrict__ out, int dout, int cin) {
    __shared__ __align__(16) float ws[8 * COUT];
    const int tx = threadIdx.x, ty = threadIdx.y, tz = threadIdx.z;
    const int tid = (tz * TY + ty) * TX + tx;
    const int gx = blockIdx.x * TX + tx;
    const int gy = blockIdx.y * TY + ty;
    const int gz = blockIdx.z * TZ + tz;
    const int din = dout * 2;
    const int din2 = din * din, din3 = din2 * din;
    const int do2 = dout * dout, do3 = do2 * dout;
    const size_t base = (size_t)(2 * gz) * din2 + (2 * gy) * din + 2 * gx;

    float acc[COUT];
#pragma unroll
    for (int c = 0; c < COUT; ++c) acc[c] = 0.f;

    for (int ci = 0; ci < cin; ++ci) {
        __syncthreads();
        const float* wc = wT + (size_t)ci * 8 * COUT;
        for (int i = tid; i < 8 * COUT; i += NT) ws[i] = wc[i];
        __syncthreads();
        const float* inc = in + (size_t)ci * din3;
        float v[8];
#pragma unroll
        for (int t = 0; t < 8; ++t) {
            int dz = t >> 2, dy = (t >> 1) & 1, dx = t & 1;
            v[t] = inc[base + (size_t)dz * din2 + dy * din + dx];
        }
#pragma unroll
        for (int t = 0; t < 8; ++t) {
            const float4* wp = (const float4*)(ws + t * COUT);
#pragma unroll
            for (int c4 = 0; c4 < COUT / 4; ++c4) {
                float4 w4 = wp[c4];
                acc[c4 * 4 + 0] = fmaf(v[t], w4.x, acc[c4 * 4 + 0]);
                acc[c4 * 4 + 1] = fmaf(v[t], w4.y, acc[c4 * 4 + 1]);
                acc[c4 * 4 + 2] = fmaf(v[t], w4.z, acc[c4 * 4 + 2]);
                acc[c4 * 4 + 3] = fmaf(v[t], w4.w, acc[c4 * 4 + 3]);
            }
        }
    }

    const size_t idx = (size_t)gz * do2 + gy * dout + gx;
#pragma unroll
    for (int c = 0; c < COUT; ++c) {
        float v = acc[c];
        if (MODE == M_RELU) v = fmaxf(v, 0.f);
        out[(size_t)c * do3 + idx] = v;
    }
}

// ---------------- gate: cx *= sigmoid(relu(2 * conv_h(hx_scaled))) ----------------
// hx is stored pre-scaled by 0.5 in d_out; conv is linear so multiply sum by 2.
__launch_bounds__(NT)
__global__ void gatek(const float* __restrict__ hx, const float* __restrict__ wT,
                      float* __restrict__ cx, int dout) {
    const int COUT = 64, CIN = 32;
    __shared__ __align__(16) float ws[8 * COUT];
    const int tx = threadIdx.x, ty = threadIdx.y, tz = threadIdx.z;
    const int tid = (tz * TY + ty) * TX + tx;
    const int gx = blockIdx.x * TX + tx;
    const int gy = blockIdx.y * TY + ty;
    const int gz = blockIdx.z * TZ + tz;
    const int din = dout * 2;
    const int din2 = din * din, din3 = din2 * din;
    const int do2 = dout * dout, do3 = do2 * dout;
    const size_t base = (size_t)(2 * gz) * din2 + (2 * gy) * din + 2 * gx;

    float acc[COUT];
#pragma unroll
    for (int c = 0; c < COUT; ++c) acc[c] = 0.f;

    for (int ci = 0; ci < CIN; ++ci) {
        __syncthreads();
        const float* wc = wT + (size_t)ci * 8 * COUT;
        for (int i = tid; i < 8 * COUT; i += NT) ws[i] = wc[i];
        __syncthreads();
        const float* inc = hx + (size_t)ci * din3;
        float v[8];
#pragma unroll
        for (int t = 0; t < 8; ++t) {
            int dz = t >> 2, dy = (t >> 1) & 1, dx = t & 1;
            v[t] = inc[base + (size_t)dz * din2 + dy * din + dx];
        }
#pragma unroll
        for (int t = 0; t < 8; ++t) {
            const float4* wp = (const float4*)(ws + t * COUT);
#pragma unroll
            for (int c4 = 0; c4 < COUT / 4; ++c4) {
                float4 w4 = wp[c4];
                acc[c4 * 4 + 0] = fmaf(v[t], w4.x, acc[c4 * 4 + 0]);
                acc[c4 * 4 + 1] = fmaf(v[t], w4.y, acc[c4 * 4 + 1]);
                acc[c4 * 4 + 2] = fmaf(v[t], w4.z, acc[c4 * 4 + 2]);
                acc[c4 * 4 + 3] = fmaf(v[t], w4.w, acc[c4 * 4 + 3]);
            }
        }
    }

    const size_t idx = (size_t)gz * do2 + gy * dout + gx;
#pragma unroll
    for (int c = 0; c < COUT; ++c) {
        float s = acc[c] * 2.f;                       // undo hx 0.5 scaling
        float g = (s > 0.f) ? 1.f / (1.f + expf(-s)) : 0.5f;  // sigmoid(relu(s))
        cx[(size_t)c * do3 + idx] *= g;
    }
}

// ---------------- driver ----------------
extern "C" void kernel_launch(void* const* d_in, const int* in_sizes, int n_in,
                              void* d_out, int out_size) {
    (void)in_sizes; (void)n_in; (void)out_size;
    const float* x     = (const float*)d_in[0];
    const float* w_h   = (const float*)d_in[1];
    const float* w_c0  = (const float*)d_in[2];
    const float* w_r0  = (const float*)d_in[3];
    const float* w_r1  = (const float*)d_in[4];
    const float* w_c1  = (const float*)d_in[5];
    const float* w_out = (const float*)d_in[6];
    float* out = (float*)d_out;

    float *wh, *wc0, *wr0, *wr1, *wc1, *wout, *bY, *bT, *bA, *bB;
    cudaGetSymbolAddress((void**)&wh,   g_wh);
    cudaGetSymbolAddress((void**)&wc0,  g_wc0);
    cudaGetSymbolAddress((void**)&wr0,  g_wr0);
    cudaGetSymbolAddress((void**)&wr1,  g_wr1);
    cudaGetSymbolAddress((void**)&wc1,  g_wc1);
    cudaGetSymbolAddress((void**)&wout, g_wout);
    cudaGetSymbolAddress((void**)&bY,   g_y);
    cudaGetSymbolAddress((void**)&bT,   g_t);
    cudaGetSymbolAddress((void**)&bA,   g_cA);
    cudaGetSymbolAddress((void**)&bB,   g_cB);

    // weight reorders (O,I,t) -> (I,t,O)
    {
        int n;
        n = 64 * 32 * 8;  reorderw<<<(n + 255) / 256, 256>>>(w_h,   wh,   64, 32, 8);
        n = 64 * 64 * 8;  reorderw<<<(n + 255) / 256, 256>>>(w_c0,  wc0,  64, 64, 8);
        n = 64 * 64 * 27; reorderw<<<(n + 255) / 256, 256>>>(w_r0,  wr0,  64, 64, 27);
        n = 64 * 64 * 27; reorderw<<<(n + 255) / 256, 256>>>(w_r1,  wr1,  64, 64, 27);
        n = 64 * 64 * 27; reorderw<<<(n + 255) / 256, 256>>>(w_c1,  wc1,  64, 64, 27);
        n = 32 * 64 * 27; reorderw<<<(n + 255) / 256, 256>>>(w_out, wout, 32, 64, 27);
    }

    const dim3 B(TX, TY, TZ);
    auto g3 = [](int d) { return dim3(d / TX, d / TY, d / TZ); };

    const size_t o0 = 0;
    const size_t o1 = o0 + (size_t)32 * 64 * 64 * 64;
    const size_t o2 = o1 + (size_t)32 * 32 * 32 * 32;
    const size_t o3 = o2 + (size_t)32 * 16 * 16 * 16;

    // feas[0] = 0.5 * conv_out(x) @ 64
    conv3k<32, M_HALF><<<g3(64), B>>>(x, wout, out + o0, 64, 64);

    // ---- iteration 1: 64 -> 32 ----
    conv2k<64, M_RELU ><<<g3(32), B>>>(x,  wc0, bY, 32, 64);
    conv3k<64, M_RELU ><<<g3(32), B>>>(bY, wr0, bT, 32, 64);
    conv3k<64, M_ADD  ><<<g3(32), B>>>(bT, wr1, bY, 32, 64);
    conv3k<64, M_PLAIN><<<g3(32), B>>>(bY, wc1, bA, 32, 64);
    gatek<<<g3(32), B>>>(out + o0, wh, bA, 32);
    conv3k<32, M_HALF ><<<g3(32), B>>>(bA, wout, out + o1, 32, 64);

    // ---- iteration 2: 32 -> 16 ----
    conv2k<64, M_RELU ><<<g3(16), B>>>(bA, wc0, bY, 16, 64);
    conv3k<64, M_RELU ><<<g3(16), B>>>(bY, wr0, bT, 16, 64);
    conv3k<64, M_ADD  ><<<g3(16), B>>>(bT, wr1, bY, 16, 64);
    conv3k<64, M_PLAIN><<<g3(16), B>>>(bY, wc1, bB, 16, 64);
    gatek<<<g3(16), B>>>(out + o1, wh, bB, 16);
    conv3k<32, M_HALF ><<<g3(16), B>>>(bB, wout, out + o2, 16, 64);

    // ---- iteration 3: 16 -> 8 ----
    conv2k<64, M_RELU ><<<g3(8), B>>>(bB, wc0, bY, 8, 64);
    conv3k<64, M_RELU ><<<g3(8), B>>>(bY, wr0, bT, 8, 64);
    conv3k<64, M_ADD  ><<<g3(8), B>>>(bT, wr1, bY, 8, 64);
    conv3k<64, M_PLAIN><<<g3(8), B>>>(bY, wc1, bA, 8, 64);
    gatek<<<g3(8), B>>>(out + o2, wh, bA, 8);
    conv3k<32, M_HALF ><<<g3(8), B>>>(bA, wout, out + o3, 8, 64);
}

// round 2
// speedup vs baseline: 3.4886x; 3.4886x over previous
#include <cuda_runtime.h>
#include <math.h>

typedef unsigned long long ull;

// ---------------- packed f32x2 helpers (sm_103a) ----------------
__device__ __forceinline__ ull ffma2(ull a, ull b, ull c) {
    ull d;
    asm("fma.rn.f32x2 %0, %1, %2, %3;" : "=l"(d) : "l"(a), "l"(b), "l"(c));
    return d;
}
__device__ __forceinline__ ull dup2(float v) {
    ull r;
    asm("mov.b64 %0, {%1, %1};" : "=l"(r) : "f"(v));
    return r;
}
__device__ __forceinline__ float2 unp2(ull a) {
    float2 f;
    asm("mov.b64 {%0, %1}, %2;" : "=f"(f.x), "=f"(f.y) : "l"(a));
    return f;
}

// ---------------- scratch (allocation-free: __device__ globals) ----------------
#define MAXBUF (64*32*32*32)          // 2,097,152 floats
__device__ float g_wh  [64*32*8];     // reordered weights [ci][tap][co]
__device__ float g_wc0 [64*64*8];
__device__ float g_wr0 [64*64*27];
__device__ float g_wr1 [64*64*27];
__device__ float g_wc1 [64*64*27];
__device__ float g_wout[32*64*27];
__device__ float g_y [MAXBUF];
__device__ float g_t [MAXBUF];
__device__ float g_cA[MAXBUF];
__device__ float g_cB[64*16*16*16];
__device__ float g_part[4*1024*1024]; // split-K partial slabs (16 MB)

enum { M_PLAIN = 0, M_RELU = 1, M_ADD = 2, M_HALF = 3, M_GATE = 4 };

// reorder weights (O,I,taps) -> (I,taps,O)
__global__ void reorderw(const float* __restrict__ w, float* __restrict__ wT,
                         int cout, int cin, int taps) {
    int i = blockIdx.x * 256 + threadIdx.x;
    int n = cout * cin * taps;
    if (i >= n) return;
    int co = i / (cin * taps);
    int r  = i % (cin * taps);
    int ci = r / taps;
    int t  = r % taps;
    wT[((size_t)ci * taps + t) * cout + co] = w[i];
}

// ---------------- k3 s1 SAME conv, 2 voxels x 32 couts per thread ----------------
// grid.z = (d/4) * ngroups * nsplit ; blockDim = (tilex/2, 8, 4)
template<int MODE>
__global__ __launch_bounds__(256, 2)
void conv3p(const float* __restrict__ in, const float* __restrict__ wT,
            float* __restrict__ out, int d, int cinT, int coutT,
            int ngroups, int nsplit) {
    __shared__ float tf[6 * 10 * 18];
    __shared__ __align__(16) float ws[27 * 32];
    const int TXv = blockDim.x;          // 8 (tilex 16) or 4 (tilex 8)
    const int tilex = TXv * 2;
    const int hx_ = tilex + 2;
    const int tx = threadIdx.x, ty = threadIdx.y, tz = threadIdx.z;
    const int nth = TXv * 32;
    const int tid = (tz * 8 + ty) * TXv + tx;

    const int gs = ngroups * nsplit;
    const int zt = blockIdx.z / gs;
    const int rem = blockIdx.z % gs;
    const int g = rem / nsplit;
    const int s = rem % nsplit;
    const int x0 = blockIdx.x * tilex, y0 = blockIdx.y * 8, z0 = zt * 4;
    const int d2 = d * d, d3 = d2 * d;
    const int cin_per = cinT / nsplit;
    const int ci0 = s * cin_per;
    const int cb = g * 32;

    ull acc[2][16];
#pragma unroll
    for (int v = 0; v < 2; ++v)
#pragma unroll
        for (int p = 0; p < 16; ++p) acc[v][p] = 0ull;

    const int hn = 6 * 10 * hx_;
    for (int ci = ci0; ci < ci0 + cin_per; ++ci) {
        __syncthreads();
        const float* inc = in + (size_t)ci * d3;
        for (int i = tid; i < hn; i += nth) {
            int lx = i % hx_;
            int r2 = i / hx_;
            int ly = r2 % 10;
            int lz = r2 / 10;
            int gx = x0 + lx - 1, gy = y0 + ly - 1, gz = z0 + lz - 1;
            float v = 0.f;
            if ((unsigned)gx < (unsigned)d && (unsigned)gy < (unsigned)d &&
                (unsigned)gz < (unsigned)d)
                v = inc[(size_t)gz * d2 + gy * d + gx];
            tf[(lz * 10 + ly) * hx_ + lx] = v;
        }
        const float* wc = wT + (size_t)ci * 27 * coutT + cb;
        for (int i = tid; i < 27 * 32; i += nth) {
            int t = i >> 5, c = i & 31;
            ws[i] = wc[(size_t)t * coutT + c];
        }
        __syncthreads();

#pragma unroll
        for (int dz = 0; dz < 3; ++dz)
#pragma unroll
            for (int dy = 0; dy < 3; ++dy) {
                const float* row = tf + ((tz + dz) * 10 + ty + dy) * hx_ + 2 * tx;
                float rr[4];
                rr[0] = row[0]; rr[1] = row[1]; rr[2] = row[2]; rr[3] = row[3];
#pragma unroll
                for (int dx = 0; dx < 3; ++dx) {
                    ull v0 = dup2(rr[dx]);
                    ull v1 = dup2(rr[dx + 1]);
                    const ulonglong2* wp =
                        (const ulonglong2*)(ws + ((dz * 3 + dy) * 3 + dx) * 32);
#pragma unroll
                    for (int p = 0; p < 8; ++p) {
                        ulonglong2 w2 = wp[p];
                        acc[0][2 * p]     = ffma2(v0, w2.x, acc[0][2 * p]);
                        acc[0][2 * p + 1] = ffma2(v0, w2.y, acc[0][2 * p + 1]);
                        acc[1][2 * p]     = ffma2(v1, w2.x, acc[1][2 * p]);
                        acc[1][2 * p + 1] = ffma2(v1, w2.y, acc[1][2 * p + 1]);
                    }
                }
            }
    }

    const int gy = y0 + ty, gz = z0 + tz;
#pragma unroll
    for (int v = 0; v < 2; ++v) {
        const int gx = x0 + 2 * tx + v;
        const size_t idx = (size_t)gz * d2 + gy * d + gx;
#pragma unroll
        for (int p = 0; p < 16; ++p) {
            float2 f = unp2(acc[v][p]);
            float vals[2] = { f.x, f.y };
#pragma unroll
            for (int h = 0; h < 2; ++h) {
                int c = cb + 2 * p + h;
                float val = vals[h];
                if (nsplit > 1) {
                    out[((size_t)s * coutT + c) * d3 + idx] = val;
                } else {
                    if (MODE == M_RELU) val = fmaxf(val, 0.f);
                    if (MODE == M_HALF) val *= 0.5f;
                    float* o = out + (size_t)c * d3 + idx;
                    if (MODE == M_ADD) *o += val; else *o = val;
                }
            }
        }
    }
}

// ---------------- k2 s2 VALID conv (also gate when MODE==M_GATE) ----------------
template<int MODE>
__global__ __launch_bounds__(256, 2)
void conv2p(const float* __restrict__ in, const float* __restrict__ wT,
            float* __restrict__ out, int dout, int cinT, int coutT,
            int ngroups, int nsplit) {
    __shared__ __align__(16) float ws[8 * 32];
    const int TXv = blockDim.x;
    const int tilex = TXv * 2;
    const int tx = threadIdx.x, ty = threadIdx.y, tz = threadIdx.z;
    const int nth = TXv * 32;
    const int tid = (tz * 8 + ty) * TXv + tx;

    const int gs = ngroups * nsplit;
    const int zt = blockIdx.z / gs;
    const int rem = blockIdx.z % gs;
    const int g = rem / nsplit;
    const int s = rem % nsplit;
    const int gx0 = blockIdx.x * tilex + 2 * tx;   // out-x of voxel 0
    const int gy = blockIdx.y * 8 + ty, gz = zt * 4 + tz;
    const int din = dout * 2;
    const int din2 = din * din, din3 = din2 * din;
    const int do2 = dout * dout, do3 = do2 * dout;
    const int cin_per = cinT / nsplit, ci0 = s * cin_per;
    const int cb = g * 32;
    const size_t ibase = ((size_t)(2 * gz) * din + 2 * gy) * din + 2 * gx0;

    ull acc[2][16];
#pragma unroll
    for (int v = 0; v < 2; ++v)
#pragma unroll
        for (int p = 0; p < 16; ++p) acc[v][p] = 0ull;

    for (int ci = ci0; ci < ci0 + cin_per; ++ci) {
        __syncthreads();
        const float* wc = wT + (size_t)ci * 8 * coutT + cb;
        for (int i = tid; i < 8 * 32; i += nth) {
            int t = i >> 5, c = i & 31;
            ws[i] = wc[(size_t)t * coutT + c];
        }
        __syncthreads();
        const float* inc = in + (size_t)ci * din3;
        float4 q[4];
#pragma unroll
        for (int t = 0; t < 4; ++t) {
            int dz = t >> 1, dy = t & 1;
            q[t] = *(const float4*)(inc + ibase + (size_t)dz * din2 + dy * din);
        }
#pragma unroll
        for (int dz = 0; dz < 2; ++dz)
#pragma unroll
            for (int dy = 0; dy < 2; ++dy)
#pragma unroll
                for (int dx = 0; dx < 2; ++dx) {
                    const float4& qq = q[dz * 2 + dy];
                    float f0 = dx ? qq.y : qq.x;
                    float f1 = dx ? qq.w : qq.z;
                    ull v0 = dup2(f0), v1 = dup2(f1);
                    const ulonglong2* wp =
                        (const ulonglong2*)(ws + (dz * 4 + dy * 2 + dx) * 32);
#pragma unroll
                    for (int p = 0; p < 8; ++p) {
                        ulonglong2 w2 = wp[p];
                        acc[0][2 * p]     = ffma2(v0, w2.x, acc[0][2 * p]);
                        acc[0][2 * p + 1] = ffma2(v0, w2.y, acc[0][2 * p + 1]);
                        acc[1][2 * p]     = ffma2(v1, w2.x, acc[1][2 * p]);
                        acc[1][2 * p + 1] = ffma2(v1, w2.y, acc[1][2 * p + 1]);
                    }
                }
    }

#pragma unroll
    for (int v = 0; v < 2; ++v) {
        const int gx = gx0 + v;
        const size_t idx = (size_t)gz * do2 + gy * dout + gx;
#pragma unroll
        for (int p = 0; p < 16; ++p) {
            float2 f = unp2(acc[v][p]);
            float vals[2] = { f.x, f.y };
#pragma unroll
            for (int h = 0; h < 2; ++h) {
                int c = cb + 2 * p + h;
                float val = vals[h];
                if (nsplit > 1) {
                    out[((size_t)s * coutT + c) * do3 + idx] = val;
                } else if (MODE == M_GATE) {
                    float s2 = 2.f * val;   // undo hx 0.5 pre-scale
                    float gt = (s2 > 0.f) ? 1.f / (1.f + expf(-s2)) : 0.5f;
                    out[(size_t)c * do3 + idx] *= gt;
                } else {
                    if (MODE == M_RELU) val = fmaxf(val, 0.f);
                    if (MODE == M_HALF) val *= 0.5f;
                    float* o = out + (size_t)c * do3 + idx;
                    if (MODE == M_ADD) *o += val; else *o = val;
                }
            }
        }
    }
}

// ---------------- split-K reduction + activation ----------------
template<int MODE>
__global__ void reducek(const float* __restrict__ part, float* __restrict__ out,
                        int n, int stride, int nsplit) {
    int i = blockIdx.x * 256 + threadIdx.x;
    if (i >= n) return;
    float sum = 0.f;
    for (int s = 0; s < nsplit; ++s) sum += part[(size_t)s * stride + i];
    if (MODE == M_PLAIN) out[i] = sum;
    else if (MODE == M_RELU) out[i] = fmaxf(sum, 0.f);
    else if (MODE == M_ADD)  out[i] += sum;
    else if (MODE == M_HALF) out[i] = 0.5f * sum;
    else { // M_GATE: out is cx; sum is conv_h(hx*0.5)
        float s2 = 2.f * sum;
        float gt = (s2 > 0.f) ? 1.f / (1.f + expf(-s2)) : 0.5f;
        out[i] *= gt;
    }
}

// ---------------- host-side launch helpers ----------------
static void run3(const float* in, const float* w, float* out,
                 int d, int cin, int cout, int mode, int nsplit) {
    int tilex = (d >= 16) ? 16 : 8;
    dim3 B(tilex / 2, 8, 4);
    dim3 G(d / tilex, d / 8, (d / 4) * (cout / 32) * nsplit);
    if (nsplit > 1) mode = M_PLAIN;
    switch (mode) {
        case M_PLAIN: conv3p<M_PLAIN><<<G, B>>>(in, w, out, d, cin, cout, cout / 32, nsplit); break;
        case M_RELU:  conv3p<M_RELU ><<<G, B>>>(in, w, out, d, cin, cout, cout / 32, nsplit); break;
        case M_ADD:   conv3p<M_ADD  ><<<G, B>>>(in, w, out, d, cin, cout, cout / 32, nsplit); break;
        default:      conv3p<M_HALF ><<<G, B>>>(in, w, out, d, cin, cout, cout / 32, nsplit); break;
    }
}

static void run2(const float* in, const float* w, float* out,
                 int dout, int cin, int cout, int mode, int nsplit) {
    int tilex = (dout >= 16) ? 16 : 8;
    dim3 B(tilex / 2, 8, 4);
    dim3 G(dout / tilex, dout / 8, (dout / 4) * (cout / 32) * nsplit);
    if (nsplit > 1) mode = M_PLAIN;
    switch (mode) {
        case M_PLAIN: conv2p<M_PLAIN><<<G, B>>>(in, w, out, dout, cin, cout, cout / 32, nsplit); break;
        case M_RELU:  conv2p<M_RELU ><<<G, B>>>(in, w, out, dout, cin, cout, cout / 32, nsplit); break;
        case M_GATE:  conv2p<M_GATE ><<<G, B>>>(in, w, out, dout, cin, cout, cout / 32, nsplit); break;
        default:      conv2p<M_HALF ><<<G, B>>>(in, w, out, dout, cin, cout, cout / 32, nsplit); break;
    }
}

static void runred(const float* part, float* out, int n, int stride, int nsplit, int mode) {
    dim3 G((n + 255) / 256);
    switch (mode) {
        case M_PLAIN: reducek<M_PLAIN><<<G, 256>>>(part, out, n, stride, nsplit); break;
        case M_RELU:  reducek<M_RELU ><<<G, 256>>>(part, out, n, stride, nsplit); break;
        case M_ADD:   reducek<M_ADD  ><<<G, 256>>>(part, out, n, stride, nsplit); break;
        case M_HALF:  reducek<M_HALF ><<<G, 256>>>(part, out, n, stride, nsplit); break;
        default:      reducek<M_GATE ><<<G, 256>>>(part, out, n, stride, nsplit); break;
    }
}

// ---------------- driver ----------------
extern "C" void kernel_launch(void* const* d_in, const int* in_sizes, int n_in,
                              void* d_out, int out_size) {
    (void)in_sizes; (void)n_in; (void)out_size;
    const float* x     = (const float*)d_in[0];
    const float* w_h   = (const float*)d_in[1];
    const float* w_c0  = (const float*)d_in[2];
    const float* w_r0  = (const float*)d_in[3];
    const float* w_r1  = (const float*)d_in[4];
    const float* w_c1  = (const float*)d_in[5];
    const float* w_out = (const float*)d_in[6];
    float* out = (float*)d_out;

    float *wh, *wc0, *wr0, *wr1, *wc1, *wout, *bY, *bT, *bA, *bB, *bP;
    cudaGetSymbolAddress((void**)&wh,   g_wh);
    cudaGetSymbolAddress((void**)&wc0,  g_wc0);
    cudaGetSymbolAddress((void**)&wr0,  g_wr0);
    cudaGetSymbolAddress((void**)&wr1,  g_wr1);
    cudaGetSymbolAddress((void**)&wc1,  g_wc1);
    cudaGetSymbolAddress((void**)&wout, g_wout);
    cudaGetSymbolAddress((void**)&bY,   g_y);
    cudaGetSymbolAddress((void**)&bT,   g_t);
    cudaGetSymbolAddress((void**)&bA,   g_cA);
    cudaGetSymbolAddress((void**)&bB,   g_cB);
    cudaGetSymbolAddress((void**)&bP,   g_part);

    {
        int n;
        n = 64 * 32 * 8;  reorderw<<<(n + 255) / 256, 256>>>(w_h,   wh,   64, 32, 8);
        n = 64 * 64 * 8;  reorderw<<<(n + 255) / 256, 256>>>(w_c0,  wc0,  64, 64, 8);
        n = 64 * 64 * 27; reorderw<<<(n + 255) / 256, 256>>>(w_r0,  wr0,  64, 64, 27);
        n = 64 * 64 * 27; reorderw<<<(n + 255) / 256, 256>>>(w_r1,  wr1,  64, 64, 27);
        n = 64 * 64 * 27; reorderw<<<(n + 255) / 256, 256>>>(w_c1,  wc1,  64, 64, 27);
        n = 32 * 64 * 27; reorderw<<<(n + 255) / 256, 256>>>(w_out, wout, 32, 64, 27);
    }

    const size_t o0 = 0;
    const size_t o1 = o0 + (size_t)32 * 64 * 64 * 64;
    const size_t o2 = o1 + (size_t)32 * 32 * 32 * 32;
    const size_t o3 = o2 + (size_t)32 * 16 * 16 * 16;

    const int d3_32 = 32 * 32 * 32, d3_16 = 16 * 16 * 16, d3_8 = 8 * 8 * 8;

    // feas[0] = 0.5 * conv_out(x) @64 : 512 blocks, no split needed
    run3(x, wout, out + o0, 64, 64, 32, M_HALF, 1);

    // ---- iteration 1: d=32, nsplit=2 ----
    run2(x, wc0, bP, 32, 64, 64, M_PLAIN, 2);
    runred(bP, bY, 64 * d3_32, 64 * d3_32, 2, M_RELU);
    run3(bY, wr0, bP, 32, 64, 64, M_PLAIN, 2);
    runred(bP, bT, 64 * d3_32, 64 * d3_32, 2, M_RELU);
    run3(bT, wr1, bP, 32, 64, 64, M_PLAIN, 2);
    runred(bP, bY, 64 * d3_32, 64 * d3_32, 2, M_ADD);
    run3(bY, wc1, bP, 32, 64, 64, M_PLAIN, 2);
    runred(bP, bA, 64 * d3_32, 64 * d3_32, 2, M_PLAIN);
    run2(out + o0, wh, bP, 32, 32, 64, M_PLAIN, 2);
    runred(bP, bA, 64 * d3_32, 64 * d3_32, 2, M_GATE);
    run3(bA, wout, bP, 32, 64, 32, M_PLAIN, 2);
    runred(bP, out + o1, 32 * d3_32, 32 * d3_32, 2, M_HALF);

    // ---- iteration 2: d=16, nsplit=8 ----
    run2(bA, wc0, bP, 16, 64, 64, M_PLAIN, 8);
    runred(bP, bY, 64 * d3_16, 64 * d3_16, 8, M_RELU);
    run3(bY, wr0, bP, 16, 64, 64, M_PLAIN, 8);
    runred(bP, bT, 64 * d3_16, 64 * d3_16, 8, M_RELU);
    run3(bT, wr1, bP, 16, 64, 64, M_PLAIN, 8);
    runred(bP, bY, 64 * d3_16, 64 * d3_16, 8, M_ADD);
    run3(bY, wc1, bP, 16, 64, 64, M_PLAIN, 8);
    runred(bP, bB, 64 * d3_16, 64 * d3_16, 8, M_PLAIN);
    run2(out + o1, wh, bP, 16, 32, 64, M_PLAIN, 8);
    runred(bP, bB, 64 * d3_16, 64 * d3_16, 8, M_GATE);
    run3(bB, wout, bP, 16, 64, 32, M_PLAIN, 8);
    runred(bP, out + o2, 32 * d3_16, 32 * d3_16, 8, M_HALF);

    // ---- iteration 3: d=8, nsplit=16 ----
    run2(bB, wc0, bP, 8, 64, 64, M_PLAIN, 16);
    runred(bP, bY, 64 * d3_8, 64 * d3_8, 16, M_RELU);
    run3(bY, wr0, bP, 8, 64, 64, M_PLAIN, 16);
    runred(bP, bT, 64 * d3_8, 64 * d3_8, 16, M_RELU);
    run3(bT, wr1, bP, 8, 64, 64, M_PLAIN, 16);
    runred(bP, bY, 64 * d3_8, 64 * d3_8, 16, M_ADD);
    run3(bY, wc1, bP, 8, 64, 64, M_PLAIN, 16);
    runred(bP, bA, 64 * d3_8, 64 * d3_8, 16, M_PLAIN);
    run2(out + o2, wh, bP, 8, 32, 64, M_PLAIN, 16);
    runred(bP, bA, 64 * d3_8, 64 * d3_8, 16, M_GATE);
    run3(bA, wout, bP, 8, 64, 32, M_PLAIN, 16);
    runred(bP, out + o3, 32 * d3_8, 32 * d3_8, 16, M_HALF);
}